// round 1
// baseline (speedup 1.0000x reference)
#include <cuda_runtime.h>

// Problem constants (fixed shapes for this problem instance)
#define BATCH 2
#define A_    2
#define C_    10
#define HW_   1024
#define NBOX  2048           // HW_ * A_
#define LOG2E 1.4426950408889634f
#define PI_F  3.14159265358979323846f

// Output layout in d_out (tuple flattened in order):
//   out_scores: [0, 40960)      = B*A*C*HW
//   bbox_preds: [40960, 69632)  = B*A*7*HW = 28672
//   pp_params : [69632, 131072) = B*C*3*HW = 61440
#define OUT_BBOX 40960
#define OUT_PP   69632

// Scratch (static __device__ arrays; no allocation)
// g_bev per (b,hw): [0:4] bev a=0 (x1,y1,x2,y2), [4:8] bev a=1, [8] area0, [9] area1, [10:12] pad
__device__ __align__(16) float g_bev[BATCH * HW_ * 12];
// g_pc per (b,hw): [0:10] p1[c], [10:12] pad, [12:32] smsc interleaved (2*c + a)
__device__ __align__(16) float g_pc[BATCH * HW_ * 32];
// g_p0 per (b,hw): p0[c] pre-scaled by log2(e)
__device__ __align__(16) float g_p0[BATCH * HW_ * 10];
__device__ float g_scinv[BATCH * C_];

__device__ __forceinline__ float ex2(float x) {
    float y;
    asm("ex2.approx.f32 %0, %1;" : "=f"(y) : "f"(x));
    return y;
}

// ---------------------------------------------------------------------------
// K1: per-(b,c) softmax denominators over n (2048 values each)
// ---------------------------------------------------------------------------
__global__ void k_scsum(const float* __restrict__ scores) {
    int b = blockIdx.x / C_;
    int c = blockIdx.x % C_;
    __shared__ float red[256];
    float s = 0.f;
    for (int m = threadIdx.x; m < NBOX; m += 256) {
        int a = m & 1, hw = m >> 1;
        s += __expf(scores[((b * A_ + a) * C_ + c) * HW_ + hw]);
    }
    red[threadIdx.x] = s;
    __syncthreads();
#pragma unroll
    for (int o = 128; o > 0; o >>= 1) {
        if (threadIdx.x < o) red[threadIdx.x] += red[threadIdx.x + o];
        __syncthreads();
    }
    if (threadIdx.x == 0) g_scinv[b * C_ + c] = 1.0f / red[0];
}

// ---------------------------------------------------------------------------
// K2: pack per-(b,hw) tables: BEV boxes + areas, p1, p0*log2e, softmaxed scores
// ---------------------------------------------------------------------------
__global__ void k_prep(const float* __restrict__ scores,
                       const float* __restrict__ pp,
                       const float* __restrict__ dec) {
    int idx = blockIdx.x * 256 + threadIdx.x;
    if (idx >= BATCH * HW_) return;
    int b = idx >> 10;
    int hw = idx & (HW_ - 1);

    float* bv = g_bev + idx * 12;
#pragma unroll
    for (int a = 0; a < 2; a++) {
        const float* d7 = dec + ((size_t)b * NBOX + hw * 2 + a) * 7;
        float x = d7[0], y = d7[1], dx = d7[3], dy = d7[4], yaw = d7[6];
        float normed = fabsf(yaw - floorf(yaw / PI_F + 0.5f) * PI_F);
        bool sw = normed > 0.25f * PI_F;
        float w = sw ? dy : dx;
        float h = sw ? dx : dy;
        float x1 = x - 0.5f * w, y1 = y - 0.5f * h;
        float x2 = x + 0.5f * w, y2 = y + 0.5f * h;
        bv[a * 4 + 0] = x1;
        bv[a * 4 + 1] = y1;
        bv[a * 4 + 2] = x2;
        bv[a * 4 + 3] = y2;
        bv[8 + a] = (x2 - x1) * (y2 - y1);  // match reference's area computation
    }
    bv[10] = 0.f;
    bv[11] = 0.f;

    float* pc = g_pc + idx * 32;
#pragma unroll
    for (int c = 0; c < C_; c++) {
        pc[c] = pp[((size_t)b * 30 + c * 3 + 1) * HW_ + hw];                 // p1
        g_p0[idx * 10 + c] = pp[((size_t)b * 30 + c * 3) * HW_ + hw] * LOG2E; // p0*log2e
    }
    pc[10] = 0.f;
    pc[11] = 0.f;
#pragma unroll
    for (int c = 0; c < C_; c++) {
#pragma unroll
        for (int a = 0; a < 2; a++) {
            float e = __expf(scores[((b * A_ + a) * C_ + c) * HW_ + hw]);
            pc[12 + 2 * c + a] = e * g_scinv[b * C_ + c];
        }
    }
}

// ---------------------------------------------------------------------------
// K3: main fused kernel. One warp per (b, hwn); lanes stride over hwm.
// ---------------------------------------------------------------------------
__device__ __forceinline__ float iou1(float ax1, float ay1, float ax2, float ay2, float aa,
                                      float bx1, float by1, float bx2, float by2, float ba) {
    float ltx = fmaxf(ax1, bx1);
    float lty = fmaxf(ay1, by1);
    float rbx = fminf(ax2, bx2);
    float rby = fminf(ay2, by2);
    float w = fmaxf(rbx - ltx, 0.f);
    float h = fmaxf(rby - lty, 0.f);
    float inter = w * h;
    float uni = fmaxf(aa + ba - inter, 1e-6f);
    return __fdividef(inter, uni);
}

__global__ void __launch_bounds__(128) k_main(float* __restrict__ out) {
    int lane = threadIdx.x & 31;
    int gw = blockIdx.x * 4 + (threadIdx.x >> 5);  // global warp id = (b, hwn)
    int b = gw >> 10;
    int hwn = gw & (HW_ - 1);

    // n-side data (loop invariant): both anchors of this cell
    const float* bvn = g_bev + (size_t)gw * 12;
    float n0x1 = bvn[0], n0y1 = bvn[1], n0x2 = bvn[2], n0y2 = bvn[3];
    float n1x1 = bvn[4], n1y1 = bvn[5], n1x2 = bvn[6], n1y2 = bvn[7];
    float an0 = bvn[8], an1 = bvn[9];

    float p0v[10];
#pragma unroll
    for (int c = 0; c < C_; c++) p0v[c] = g_p0[(size_t)gw * 10 + c];

    float acc0[10], acc1[10], sm0[10], sm1[10];
#pragma unroll
    for (int c = 0; c < C_; c++) { acc0[c] = 0.f; acc1[c] = 0.f; sm0[c] = 0.f; sm1[c] = 0.f; }

    const float* bevb = g_bev + (size_t)(b * HW_) * 12;
    const float* pcb = g_pc + (size_t)(b * HW_) * 32;

    for (int hwm = lane; hwm < HW_; hwm += 32) {
        const float* bv = bevb + hwm * 12;
        float4 B0 = *(const float4*)(bv);
        float4 B1 = *(const float4*)(bv + 4);
        float2 AR = *(const float2*)(bv + 8);

        float i00 = iou1(n0x1, n0y1, n0x2, n0y2, an0, B0.x, B0.y, B0.z, B0.w, AR.x);
        float i01 = iou1(n0x1, n0y1, n0x2, n0y2, an0, B1.x, B1.y, B1.z, B1.w, AR.y);
        float i10 = iou1(n1x1, n1y1, n1x2, n1y2, an1, B0.x, B0.y, B0.z, B0.w, AR.x);
        float i11 = iou1(n1x1, n1y1, n1x2, n1y2, an1, B1.x, B1.y, B1.z, B1.w, AR.y);

        float e00 = ex2(i00 * LOG2E);
        float e01 = ex2(i01 * LOG2E);
        float e10 = ex2(i10 * LOG2E);
        float e11 = ex2(i11 * LOG2E);
        float es0 = e00 + e01;
        float es1 = e10 + e11;

        const float4* pc4 = (const float4*)(pcb + hwm * 32);
        float p1v[12], wv[20];
        *(float4*)&p1v[0] = pc4[0];
        *(float4*)&p1v[4] = pc4[1];
        *(float4*)&p1v[8] = pc4[2];
        *(float4*)&wv[0] = pc4[3];
        *(float4*)&wv[4] = pc4[4];
        *(float4*)&wv[8] = pc4[5];
        *(float4*)&wv[12] = pc4[6];
        *(float4*)&wv[16] = pc4[7];

#pragma unroll
        for (int c = 0; c < C_; c++) {
            float eb = ex2(p0v[c] * p1v[c]);   // exp(p0*p1), log2e folded into p0
            float w0 = wv[2 * c], w1 = wv[2 * c + 1];
            float s0 = e00 * w0 + e01 * w1;
            float s1 = e10 * w0 + e11 * w1;
            acc0[c] += eb * s0;
            acc1[c] += eb * s1;
            sm0[c] += eb * es0;
            sm1[c] += eb * es1;
        }
    }

    // warp butterfly reduction of all 40 accumulators
#pragma unroll
    for (int o = 16; o > 0; o >>= 1) {
#pragma unroll
        for (int c = 0; c < C_; c++) {
            acc0[c] += __shfl_xor_sync(0xffffffffu, acc0[c], o);
            acc1[c] += __shfl_xor_sync(0xffffffffu, acc1[c], o);
            sm0[c] += __shfl_xor_sync(0xffffffffu, sm0[c], o);
            sm1[c] += __shfl_xor_sync(0xffffffffu, sm1[c], o);
        }
    }

    if (lane == 0) {
#pragma unroll
        for (int c = 0; c < C_; c++) {
            out[((b * A_ + 0) * C_ + c) * HW_ + hwn] = __fdividef(acc0[c], sm0[c]);
            out[((b * A_ + 1) * C_ + c) * HW_ + hwn] = __fdividef(acc1[c], sm1[c]);
        }
    }
}

// ---------------------------------------------------------------------------
// Pass-through copies (float4 granularity)
// ---------------------------------------------------------------------------
__global__ void k_copy(const float4* __restrict__ src, float4* __restrict__ dst, int n4) {
    int i = blockIdx.x * 256 + threadIdx.x;
    if (i < n4) dst[i] = src[i];
}

extern "C" void kernel_launch(void* const* d_in, const int* in_sizes, int n_in,
                              void* d_out, int out_size) {
    const float* scores = (const float*)d_in[0];
    const float* bbox = (const float*)d_in[1];
    const float* pp = (const float*)d_in[2];
    const float* dec = (const float*)d_in[3];
    float* out = (float*)d_out;

    k_scsum<<<BATCH * C_, 256>>>(scores);
    k_prep<<<(BATCH * HW_ + 255) / 256, 256>>>(scores, pp, dec);
    k_main<<<BATCH * HW_ / 4, 128>>>(out);
    k_copy<<<28, 256>>>((const float4*)bbox, (float4*)(out + OUT_BBOX), 28672 / 4);
    k_copy<<<60, 256>>>((const float4*)pp, (float4*)(out + OUT_PP), 61440 / 4);
}

// round 2
// speedup vs baseline: 2.7723x; 2.7723x over previous
#include <cuda_runtime.h>
#include <cstdint>

// Problem constants
#define BATCH 2
#define A_    2
#define C_    10
#define HW_   1024
#define NBOX  2048
#define TILE  128
#define LOG2E 1.4426950408889634f
#define PI_F  3.14159265358979323846f

// Output layout: out_scores [0,40960) | bbox [40960,69632) | pp [69632,131072)
#define OUT_BBOX 40960
#define OUT_PP   69632

// Scratch tables (static device arrays)
// g_bev per (b,hw): 8 floats = bev(a=0) x1,y1,x2,y2 ; bev(a=1)
__device__ __align__(16) float g_bev[BATCH * HW_ * 8];
// g_pc per (b,hw): 36 floats = [0:20) raw exp(score) interleaved (2c+a),
//                              [20:30) p1[c], [30:32) area0,area1, [32:36) pad
__device__ __align__(16) float g_pc[BATCH * HW_ * 36];
// g_p0 per (b,hw): p0[c] * log2(e)
__device__ __align__(16) float g_p0[BATCH * HW_ * 10];
__device__ float g_scinv[BATCH * C_];

// ---------------- helpers ----------------
__device__ __forceinline__ float ex2(float x) {
    float y; asm("ex2.approx.f32 %0, %1;" : "=f"(y) : "f"(x)); return y;
}
typedef unsigned long long ull;
__device__ __forceinline__ ull pk(float a, float b) {
    ull r; asm("mov.b64 %0, {%1,%2};" : "=l"(r) : "f"(a), "f"(b)); return r;
}
__device__ __forceinline__ void upk(ull v, float& a, float& b) {
    asm("mov.b64 {%0,%1}, %2;" : "=f"(a), "=f"(b) : "l"(v));
}
__device__ __forceinline__ ull mul2(ull a, ull b) {
    ull r; asm("mul.rn.f32x2 %0, %1, %2;" : "=l"(r) : "l"(a), "l"(b)); return r;
}
__device__ __forceinline__ ull fma2(ull a, ull b, ull c) {
    ull r; asm("fma.rn.f32x2 %0, %1, %2, %3;" : "=l"(r) : "l"(a), "l"(b), "l"(c)); return r;
}
__device__ __forceinline__ ull add2(ull a, ull b) {
    ull r; asm("add.rn.f32x2 %0, %1, %2;" : "=l"(r) : "l"(a), "l"(b)); return r;
}
__device__ __forceinline__ void cpasync16(uint32_t saddr, const void* g) {
    asm volatile("cp.async.cg.shared.global [%0], [%1], 16;" :: "r"(saddr), "l"(g));
}

// ---------------------------------------------------------------------------
// K1 fused: prep tables (blocks 0..7) + softmax denominators (blocks 8..27)
//           + bbox copy (28..55) + pp copy (56..115)
// ---------------------------------------------------------------------------
__global__ void k_fused(const float* __restrict__ scores,
                        const float* __restrict__ bbox,
                        const float* __restrict__ pp,
                        const float* __restrict__ dec,
                        float* __restrict__ out) {
    int blk = blockIdx.x;
    int tid = threadIdx.x;

    if (blk < 8) {
        // ---- prep: one (b,hw) cell per thread ----
        int idx = blk * 256 + tid;
        int b = idx >> 10;
        int hw = idx & (HW_ - 1);

        float* bv = g_bev + (size_t)idx * 8;
        float* pc = g_pc + (size_t)idx * 36;
#pragma unroll
        for (int a = 0; a < 2; a++) {
            const float* d7 = dec + ((size_t)b * NBOX + hw * 2 + a) * 7;
            float x = d7[0], y = d7[1], dx = d7[3], dy = d7[4], yaw = d7[6];
            float normed = fabsf(yaw - floorf(yaw / PI_F + 0.5f) * PI_F);
            bool sw = normed > 0.25f * PI_F;
            float w = sw ? dy : dx;
            float h = sw ? dx : dy;
            float x1 = x - 0.5f * w, y1 = y - 0.5f * h;
            float x2 = x + 0.5f * w, y2 = y + 0.5f * h;
            bv[a * 4 + 0] = x1; bv[a * 4 + 1] = y1;
            bv[a * 4 + 2] = x2; bv[a * 4 + 3] = y2;
            pc[30 + a] = (x2 - x1) * (y2 - y1);
        }
        pc[32] = 0.f; pc[33] = 0.f; pc[34] = 0.f; pc[35] = 0.f;
#pragma unroll
        for (int c = 0; c < C_; c++) {
            pc[2 * c + 0] = __expf(scores[((b * A_ + 0) * C_ + c) * HW_ + hw]);
            pc[2 * c + 1] = __expf(scores[((b * A_ + 1) * C_ + c) * HW_ + hw]);
            pc[20 + c]    = pp[((size_t)b * 30 + c * 3 + 1) * HW_ + hw];
            g_p0[(size_t)idx * 10 + c] =
                pp[((size_t)b * 30 + c * 3) * HW_ + hw] * LOG2E;
        }
    } else if (blk < 28) {
        // ---- score softmax denominators: one (b,c) per block ----
        int s = blk - 8;
        int b = s / C_, c = s % C_;
        __shared__ float red[256];
        float acc = 0.f;
        for (int m = tid; m < NBOX; m += 256) {
            int a = m & 1, hw = m >> 1;
            acc += __expf(scores[((b * A_ + a) * C_ + c) * HW_ + hw]);
        }
        red[tid] = acc;
        __syncthreads();
#pragma unroll
        for (int o = 128; o > 0; o >>= 1) {
            if (tid < o) red[tid] += red[tid + o];
            __syncthreads();
        }
        if (tid == 0) g_scinv[b * C_ + c] = 1.0f / red[0];
    } else if (blk < 56) {
        // ---- bbox passthrough: 28 blocks * 256 f4 = 7168 f4 = 28672 floats ----
        int i = (blk - 28) * 256 + tid;
        ((float4*)(out + OUT_BBOX))[i] = ((const float4*)bbox)[i];
    } else {
        // ---- pp passthrough: 60 blocks * 256 f4 = 15360 f4 = 61440 floats ----
        int i = (blk - 56) * 256 + tid;
        ((float4*)(out + OUT_PP))[i] = ((const float4*)pp)[i];
    }
}

// ---------------------------------------------------------------------------
// K2 main: one warp per (b, hwn), m-side tables staged in smem (double buffer)
// ---------------------------------------------------------------------------
__device__ __forceinline__ float iou1(float ax1, float ay1, float ax2, float ay2, float aa,
                                      float bx1, float by1, float bx2, float by2, float ba) {
    float ltx = fmaxf(ax1, bx1);
    float lty = fmaxf(ay1, by1);
    float rbx = fminf(ax2, bx2);
    float rby = fminf(ay2, by2);
    float w = fmaxf(rbx - ltx, 0.f);
    float h = fmaxf(rby - lty, 0.f);
    float inter = w * h;
    float uni = fmaxf(aa + ba - inter, 1e-6f);
    return __fdividef(inter, uni);
}

__global__ void __launch_bounds__(128, 4) k_main(float* __restrict__ out) {
    // smem: bev 128*8*4 = 4KB, pc 128*36*4 = 18KB per buffer -> 44KB total
    __shared__ __align__(16) float sb[2][TILE * 8];
    __shared__ __align__(16) float sp[2][TILE * 36];

    int tid = threadIdx.x;
    int lane = tid & 31;
    int gw = blockIdx.x * 4 + (tid >> 5);   // (b, hwn)
    int b = gw >> 10;
    int hwn = gw & (HW_ - 1);

    // n-side invariants
    const float* bvn = g_bev + (size_t)gw * 8;
    float n0x1 = bvn[0], n0y1 = bvn[1], n0x2 = bvn[2], n0y2 = bvn[3];
    float n1x1 = bvn[4], n1y1 = bvn[5], n1x2 = bvn[6], n1y2 = bvn[7];
    const float* pcn = g_pc + (size_t)gw * 36;
    float an0 = pcn[30], an1 = pcn[31];

    ull p0p[5];
#pragma unroll
    for (int k = 0; k < 5; k++)
        p0p[k] = pk(g_p0[(size_t)gw * 10 + 2 * k], g_p0[(size_t)gw * 10 + 2 * k + 1]);

    ull acc0p[5], acc1p[5], sm0p[5], sm1p[5];
#pragma unroll
    for (int k = 0; k < 5; k++) { acc0p[k] = 0ull; acc1p[k] = 0ull; sm0p[k] = 0ull; sm1p[k] = 0ull; }

    const float4* gb4 = (const float4*)(g_bev + (size_t)b * HW_ * 8);
    const float4* gp4 = (const float4*)(g_pc + (size_t)b * HW_ * 36);

    // prefetch tile 0
    {
        uint32_t sba = (uint32_t)__cvta_generic_to_shared(&sb[0][0]);
        uint32_t spa = (uint32_t)__cvta_generic_to_shared(&sp[0][0]);
#pragma unroll
        for (int k = 0; k < 2; k++)
            cpasync16(sba + (tid + k * 128) * 16, gb4 + tid + k * 128);
#pragma unroll
        for (int k = 0; k < 9; k++)
            cpasync16(spa + (tid + k * 128) * 16, gp4 + tid + k * 128);
        asm volatile("cp.async.commit_group;");
    }

    for (int t = 0; t < 8; t++) {
        if (t < 7) {
            int nb = (t + 1) & 1;
            uint32_t sba = (uint32_t)__cvta_generic_to_shared(&sb[nb][0]);
            uint32_t spa = (uint32_t)__cvta_generic_to_shared(&sp[nb][0]);
            const float4* gbt = gb4 + (t + 1) * TILE * 2;   // 8 floats = 2 f4/cell
            const float4* gpt = gp4 + (t + 1) * TILE * 9;   // 36 floats = 9 f4/cell
#pragma unroll
            for (int k = 0; k < 2; k++)
                cpasync16(sba + (tid + k * 128) * 16, gbt + tid + k * 128);
#pragma unroll
            for (int k = 0; k < 9; k++)
                cpasync16(spa + (tid + k * 128) * 16, gpt + tid + k * 128);
            asm volatile("cp.async.commit_group;");
            asm volatile("cp.async.wait_group 1;");
        } else {
            asm volatile("cp.async.wait_group 0;");
        }
        __syncthreads();

        const float* SB = sb[t & 1];
        const float* SP = sp[t & 1];
#pragma unroll
        for (int j = 0; j < 4; j++) {
            int m = lane + j * 32;
            const float* bp = SB + m * 8;
            const float* pm = SP + m * 36;
            float4 B0 = *(const float4*)(bp);
            float4 B1 = *(const float4*)(bp + 4);
            float2 AR = *(const float2*)(pm + 30);

            float i00 = iou1(n0x1, n0y1, n0x2, n0y2, an0, B0.x, B0.y, B0.z, B0.w, AR.x);
            float i01 = iou1(n0x1, n0y1, n0x2, n0y2, an0, B1.x, B1.y, B1.z, B1.w, AR.y);
            float i10 = iou1(n1x1, n1y1, n1x2, n1y2, an1, B0.x, B0.y, B0.z, B0.w, AR.x);
            float i11 = iou1(n1x1, n1y1, n1x2, n1y2, an1, B1.x, B1.y, B1.z, B1.w, AR.y);

            float e00 = ex2(i00 * LOG2E);
            float e01 = ex2(i01 * LOG2E);
            float e10 = ex2(i10 * LOG2E);
            float e11 = ex2(i11 * LOG2E);
            float es0 = e00 + e01;
            float es1 = e10 + e11;

            ull e00s = pk(e00, e00), e01s = pk(e01, e01);
            ull e10s = pk(e10, e10), e11s = pk(e11, e11);
            ull es0s = pk(es0, es0), es1s = pk(es1, es1);

#pragma unroll
            for (int k = 0; k < 5; k++) {
                float2 p1p2 = *(const float2*)(pm + 20 + 2 * k);
                ull tt = mul2(p0p[k], pk(p1p2.x, p1p2.y));
                float t0, t1; upk(tt, t0, t1);
                ull ebp = pk(ex2(t0), ex2(t1));           // exp(bias) for c=2k,2k+1

                float4 wq = *(const float4*)(pm + 4 * k); // e00w,e01w,e00w',e01w'
                ull w0p = pk(wq.x, wq.z);
                ull w1p = pk(wq.y, wq.w);
                ull s0p = fma2(e01s, w1p, mul2(e00s, w0p));
                ull s1p = fma2(e11s, w1p, mul2(e10s, w0p));
                acc0p[k] = fma2(ebp, s0p, acc0p[k]);
                acc1p[k] = fma2(ebp, s1p, acc1p[k]);
                sm0p[k]  = fma2(ebp, es0s, sm0p[k]);
                sm1p[k]  = fma2(ebp, es1s, sm1p[k]);
            }
        }
        __syncthreads();
    }

    // warp butterfly reduction on packed accumulators
#pragma unroll
    for (int o = 16; o > 0; o >>= 1) {
#pragma unroll
        for (int k = 0; k < 5; k++) {
            acc0p[k] = add2(acc0p[k], __shfl_xor_sync(0xffffffffu, acc0p[k], o));
            acc1p[k] = add2(acc1p[k], __shfl_xor_sync(0xffffffffu, acc1p[k], o));
            sm0p[k]  = add2(sm0p[k],  __shfl_xor_sync(0xffffffffu, sm0p[k],  o));
            sm1p[k]  = add2(sm1p[k],  __shfl_xor_sync(0xffffffffu, sm1p[k],  o));
        }
    }

    if (lane == 0) {
#pragma unroll
        for (int k = 0; k < 5; k++) {
            float a0, a1, b0, b1, q0, q1, r0, r1;
            upk(acc0p[k], a0, a1);
            upk(sm0p[k],  q0, q1);
            upk(acc1p[k], b0, b1);
            upk(sm1p[k],  r0, r1);
            int c0 = 2 * k, c1 = 2 * k + 1;
            float i0 = g_scinv[b * C_ + c0];
            float i1 = g_scinv[b * C_ + c1];
            out[((b * A_ + 0) * C_ + c0) * HW_ + hwn] = __fdividef(a0, q0) * i0;
            out[((b * A_ + 0) * C_ + c1) * HW_ + hwn] = __fdividef(a1, q1) * i1;
            out[((b * A_ + 1) * C_ + c0) * HW_ + hwn] = __fdividef(b0, r0) * i0;
            out[((b * A_ + 1) * C_ + c1) * HW_ + hwn] = __fdividef(b1, r1) * i1;
        }
    }
}

extern "C" void kernel_launch(void* const* d_in, const int* in_sizes, int n_in,
                              void* d_out, int out_size) {
    const float* scores = (const float*)d_in[0];
    const float* bbox = (const float*)d_in[1];
    const float* pp = (const float*)d_in[2];
    const float* dec = (const float*)d_in[3];
    float* out = (float*)d_out;

    k_fused<<<116, 256>>>(scores, bbox, pp, dec, out);
    k_main<<<BATCH * HW_ / 4, 128>>>(out);
}

// round 6
// speedup vs baseline: 3.0067x; 1.0845x over previous
#include <cuda_runtime.h>
#include <cstdint>

// Problem constants
#define BATCH 2
#define A_    2
#define C_    10
#define HW_   1024
#define NBOX  2048
#define TILE  128
#define LOG2E 1.4426950408889634f
#define PI_F  3.14159265358979323846f

// Output layout: out_scores [0,40960) | bbox [40960,69632) | pp [69632,131072)
#define OUT_BBOX 40960
#define OUT_PP   69632

// ---------------- scratch tables (SoA-group layouts) ----------------
// g_bev4: [b][2][HW] float4
//   g0 = (x1a0, x1a1, y1a0, y1a1)   g1 = (x2a0, x2a1, y2a0, y2a1)
__device__ __align__(16) float4 g_bev4[BATCH * 2 * HW_];
// g_pc4: [b][8][HW] float4
//   g=0..4 : (w[2k,a0], w[2k+1,a0], w[2k,a1], w[2k+1,a1])   (w = exp(score))
//   g=5    : (p1[0],p1[1],p1[2],p1[3])
//   g=6    : (p1[4],p1[5],p1[6],p1[7])
//   g=7    : (p1[8],p1[9],area_a0,area_a1)
__device__ __align__(16) float4 g_pc4[BATCH * 8 * HW_];
// g_p0: [b*HW][10]  (p0[c] * log2e)
__device__ __align__(8) float g_p0[BATCH * HW_ * 10];
__device__ float g_scinv[BATCH * C_];

// ---------------- helpers ----------------
typedef unsigned long long ull;
__device__ __forceinline__ float ex2(float x) {
    float y; asm("ex2.approx.f32 %0, %1;" : "=f"(y) : "f"(x)); return y;
}
__device__ __forceinline__ float rcpf(float x) {
    float y; asm("rcp.approx.f32 %0, %1;" : "=f"(y) : "f"(x)); return y;
}
__device__ __forceinline__ ull pk(float a, float b) {
    ull r; asm("mov.b64 %0, {%1,%2};" : "=l"(r) : "f"(a), "f"(b)); return r;
}
__device__ __forceinline__ void upk(ull v, float& a, float& b) {
    asm("mov.b64 {%0,%1}, %2;" : "=f"(a), "=f"(b) : "l"(v));
}
__device__ __forceinline__ ull mul2(ull a, ull b) {
    ull r; asm("mul.rn.f32x2 %0, %1, %2;" : "=l"(r) : "l"(a), "l"(b)); return r;
}
__device__ __forceinline__ ull fma2(ull a, ull b, ull c) {
    ull r; asm("fma.rn.f32x2 %0, %1, %2, %3;" : "=l"(r) : "l"(a), "l"(b), "l"(c)); return r;
}
__device__ __forceinline__ ull add2(ull a, ull b) {
    ull r; asm("add.rn.f32x2 %0, %1, %2;" : "=l"(r) : "l"(a), "l"(b)); return r;
}
__device__ __forceinline__ void cpasync16(uint32_t saddr, const void* g) {
    asm volatile("cp.async.cg.shared.global [%0], [%1], 16;" :: "r"(saddr), "l"(g));
}

// ---------------------------------------------------------------------------
// K1 fused: prep tables (blocks 0..7) + score softmax denominators (8..27)
// ---------------------------------------------------------------------------
__global__ void k_fused(const float* __restrict__ scores,
                        const float* __restrict__ pp,
                        const float* __restrict__ dec) {
    int blk = blockIdx.x;
    int tid = threadIdx.x;

    if (blk < 8) {
        int idx = blk * 256 + tid;
        int b = idx >> 10;
        int hw = idx & (HW_ - 1);

        float x1a[2], y1a[2], x2a[2], y2a[2], area[2];
#pragma unroll
        for (int a = 0; a < 2; a++) {
            const float* d7 = dec + ((size_t)b * NBOX + hw * 2 + a) * 7;
            float x = d7[0], y = d7[1], dx = d7[3], dy = d7[4], yaw = d7[6];
            float normed = fabsf(yaw - floorf(yaw / PI_F + 0.5f) * PI_F);
            bool sw = normed > 0.25f * PI_F;
            float w = sw ? dy : dx;
            float h = sw ? dx : dy;
            x1a[a] = x - 0.5f * w; y1a[a] = y - 0.5f * h;
            x2a[a] = x + 0.5f * w; y2a[a] = y + 0.5f * h;
            area[a] = (x2a[a] - x1a[a]) * (y2a[a] - y1a[a]);
        }
        float4* bv = g_bev4 + (size_t)b * 2 * HW_ + hw;
        bv[0]    = make_float4(x1a[0], x1a[1], y1a[0], y1a[1]);
        bv[HW_]  = make_float4(x2a[0], x2a[1], y2a[0], y2a[1]);

        float e[C_][2], p1[C_];
#pragma unroll
        for (int c = 0; c < C_; c++) {
            e[c][0] = __expf(scores[((b * A_ + 0) * C_ + c) * HW_ + hw]);
            e[c][1] = __expf(scores[((b * A_ + 1) * C_ + c) * HW_ + hw]);
            p1[c]   = pp[((size_t)b * 30 + c * 3 + 1) * HW_ + hw];
            g_p0[(size_t)idx * 10 + c] =
                pp[((size_t)b * 30 + c * 3) * HW_ + hw] * LOG2E;
        }
        float4* pc = g_pc4 + (size_t)b * 8 * HW_ + hw;
#pragma unroll
        for (int k = 0; k < 5; k++)
            pc[k * HW_] = make_float4(e[2 * k][0], e[2 * k + 1][0],
                                      e[2 * k][1], e[2 * k + 1][1]);
        pc[5 * HW_] = make_float4(p1[0], p1[1], p1[2], p1[3]);
        pc[6 * HW_] = make_float4(p1[4], p1[5], p1[6], p1[7]);
        pc[7 * HW_] = make_float4(p1[8], p1[9], area[0], area[1]);
    } else {
        int s = blk - 8;
        int b = s / C_, c = s % C_;
        __shared__ float red[256];
        float acc = 0.f;
        for (int m = tid; m < NBOX; m += 256) {
            int a = m & 1, hw = m >> 1;
            acc += __expf(scores[((b * A_ + a) * C_ + c) * HW_ + hw]);
        }
        red[tid] = acc;
        __syncthreads();
#pragma unroll
        for (int o = 128; o > 0; o >>= 1) {
            if (tid < o) red[tid] += red[tid + o];
            __syncthreads();
        }
        if (tid == 0) g_scinv[b * C_ + c] = 1.0f / red[0];
    }
}

// ---------------------------------------------------------------------------
// K2 main: one warp per (b,hwn); m-tiles staged in conflict-free SoA smem.
//          Blocks >= 512 do the bbox/pp pass-through copies (overlapped).
// ---------------------------------------------------------------------------
// scalar IoU, returns iou * log2(e)
__device__ __forceinline__ float iou1(float ax1, float ay1, float ax2, float ay2, float aa,
                                      float bx1, float by1, float bx2, float by2, float ba) {
    float ltx = fmaxf(ax1, bx1);
    float lty = fmaxf(ay1, by1);
    float rbx = fminf(ax2, bx2);
    float rby = fminf(ay2, by2);
    float w = fmaxf(rbx - ltx, 0.f);
    float h = fmaxf(rby - lty, 0.f);
    float inter = w * h;
    float uni = fmaxf(aa + ba - inter, 1e-6f);
    return inter * LOG2E * rcpf(uni);
}

__global__ void __launch_bounds__(128, 4) k_main(
        const float* __restrict__ bbox, const float* __restrict__ pp,
        float* __restrict__ out) {
    if (blockIdx.x >= 512) {
        // pass-through copies: 88 blocks * 256 float4 = 22528 f4
        int base = (blockIdx.x - 512) * 256 + threadIdx.x;
#pragma unroll
        for (int r = 0; r < 2; r++) {
            int i = base + r * 128;
            if (i < 7168)
                ((float4*)(out + OUT_BBOX))[i] = ((const float4*)bbox)[i];
            else
                ((float4*)(out + OUT_PP))[i - 7168] = ((const float4*)pp)[i - 7168];
        }
        return;
    }

    __shared__ __align__(16) ulonglong2 sb[2][2 * TILE];  // bev groups
    __shared__ __align__(16) ulonglong2 sp[2][8 * TILE];  // pc groups

    int tid = threadIdx.x;
    int lane = tid & 31;
    int gw = blockIdx.x * 4 + (tid >> 5);
    int b = gw >> 10;
    int hwn = gw & (HW_ - 1);

    // n-side invariants
    float4 ng0 = g_bev4[(size_t)b * 2 * HW_ + hwn];
    float4 ng1 = g_bev4[(size_t)b * 2 * HW_ + HW_ + hwn];
    float4 ng7 = g_pc4[(size_t)b * 8 * HW_ + 7 * HW_ + hwn];
    float n0x1 = ng0.x, n1x1 = ng0.y, n0y1 = ng0.z, n1y1 = ng0.w;
    float n0x2 = ng1.x, n1x2 = ng1.y, n0y2 = ng1.z, n1y2 = ng1.w;
    float an0 = ng7.z, an1 = ng7.w;

    ull p0p[5];
#pragma unroll
    for (int k = 0; k < 5; k++) {
        float2 t = *(const float2*)(g_p0 + (size_t)gw * 10 + 2 * k);
        p0p[k] = pk(t.x, t.y);
    }

    ull acc0p[5], acc1p[5], sm0p[5], sm1p[5];
#pragma unroll
    for (int k = 0; k < 5; k++) { acc0p[k] = 0; acc1p[k] = 0; sm0p[k] = 0; sm1p[k] = 0; }

    const float4* gb = g_bev4 + (size_t)b * 2 * HW_;
    const float4* gp = g_pc4 + (size_t)b * 8 * HW_;

    // prefetch tile 0
    {
        uint32_t sba = (uint32_t)__cvta_generic_to_shared(&sb[0][0]);
        uint32_t spa = (uint32_t)__cvta_generic_to_shared(&sp[0][0]);
#pragma unroll
        for (int g = 0; g < 2; g++)
            cpasync16(sba + (g * TILE + tid) * 16, gb + g * HW_ + tid);
#pragma unroll
        for (int g = 0; g < 8; g++)
            cpasync16(spa + (g * TILE + tid) * 16, gp + g * HW_ + tid);
        asm volatile("cp.async.commit_group;");
    }

    for (int t = 0; t < 8; t++) {
        if (t < 7) {
            int nb = (t + 1) & 1;
            uint32_t sba = (uint32_t)__cvta_generic_to_shared(&sb[nb][0]);
            uint32_t spa = (uint32_t)__cvta_generic_to_shared(&sp[nb][0]);
            int off = (t + 1) * TILE + tid;
#pragma unroll
            for (int g = 0; g < 2; g++)
                cpasync16(sba + (g * TILE + tid) * 16, gb + g * HW_ + off);
#pragma unroll
            for (int g = 0; g < 8; g++)
                cpasync16(spa + (g * TILE + tid) * 16, gp + g * HW_ + off);
            asm volatile("cp.async.commit_group;");
            asm volatile("cp.async.wait_group 1;");
        } else {
            asm volatile("cp.async.wait_group 0;");
        }
        __syncthreads();

        const ulonglong2* SB = sb[t & 1];
        const ulonglong2* SP = sp[t & 1];
#pragma unroll
        for (int j = 0; j < 4; j++) {
            int m = lane + j * 32;
            ulonglong2 bg0 = SB[m];            // (x1a0,x1a1) , (y1a0,y1a1)
            ulonglong2 bg1 = SB[TILE + m];     // (x2a0,x2a1) , (y2a0,y2a1)
            ulonglong2 G7  = SP[7 * TILE + m]; // (p1[8],p1[9]) , (area0,area1)

            float bx1a0, bx1a1, by1a0, by1a1, bx2a0, bx2a1, by2a0, by2a1;
            upk(bg0.x, bx1a0, bx1a1);
            upk(bg0.y, by1a0, by1a1);
            upk(bg1.x, bx2a0, bx2a1);
            upk(bg1.y, by2a0, by2a1);
            float am0, am1;
            upk(G7.y, am0, am1);

            float q00 = iou1(n0x1, n0y1, n0x2, n0y2, an0, bx1a0, by1a0, bx2a0, by2a0, am0);
            float q01 = iou1(n0x1, n0y1, n0x2, n0y2, an0, bx1a1, by1a1, bx2a1, by2a1, am1);
            float q10 = iou1(n1x1, n1y1, n1x2, n1y2, an1, bx1a0, by1a0, bx2a0, by2a0, am0);
            float q11 = iou1(n1x1, n1y1, n1x2, n1y2, an1, bx1a1, by1a1, bx2a1, by2a1, am1);

            float e00 = ex2(q00), e01 = ex2(q01);
            float e10 = ex2(q10), e11 = ex2(q11);
            ull e00s = pk(e00, e00), e01s = pk(e01, e01);
            ull e10s = pk(e10, e10), e11s = pk(e11, e11);
            ull es0s = pk(e00 + e01, e00 + e01);
            ull es1s = pk(e10 + e11, e10 + e11);

            ulonglong2 G5 = SP[5 * TILE + m];
            ulonglong2 G6 = SP[6 * TILE + m];
            ull p1p[5] = { G5.x, G5.y, G6.x, G6.y, G7.x };

#pragma unroll
            for (int k = 0; k < 5; k++) {
                ull tt = mul2(p0p[k], p1p[k]);
                float b0, b1; upk(tt, b0, b1);
                ull ebp = pk(ex2(b0), ex2(b1));        // exp(bias) c-pair

                ulonglong2 Wk = SP[k * TILE + m];      // w0p = a0 pair, w1p = a1 pair
                ull s0p = fma2(e01s, Wk.y, mul2(e00s, Wk.x));
                ull s1p = fma2(e11s, Wk.y, mul2(e10s, Wk.x));
                acc0p[k] = fma2(ebp, s0p, acc0p[k]);
                acc1p[k] = fma2(ebp, s1p, acc1p[k]);
                sm0p[k]  = fma2(ebp, es0s, sm0p[k]);
                sm1p[k]  = fma2(ebp, es1s, sm1p[k]);
            }
        }
        __syncthreads();
    }

    // warp butterfly reduction
#pragma unroll
    for (int o = 16; o > 0; o >>= 1) {
#pragma unroll
        for (int k = 0; k < 5; k++) {
            acc0p[k] = add2(acc0p[k], __shfl_xor_sync(0xffffffffu, acc0p[k], o));
            acc1p[k] = add2(acc1p[k], __shfl_xor_sync(0xffffffffu, acc1p[k], o));
            sm0p[k]  = add2(sm0p[k],  __shfl_xor_sync(0xffffffffu, sm0p[k],  o));
            sm1p[k]  = add2(sm1p[k],  __shfl_xor_sync(0xffffffffu, sm1p[k],  o));
        }
    }

    if (lane == 0) {
#pragma unroll
        for (int k = 0; k < 5; k++) {
            float a0, a1, c0v, c1v, q0, q1, r0, r1;
            upk(acc0p[k], a0, a1);
            upk(sm0p[k],  q0, q1);
            upk(acc1p[k], c0v, c1v);
            upk(sm1p[k],  r0, r1);
            int c0 = 2 * k, c1 = 2 * k + 1;
            float i0 = g_scinv[b * C_ + c0];
            float i1 = g_scinv[b * C_ + c1];
            out[((b * A_ + 0) * C_ + c0) * HW_ + hwn] = a0 * rcpf(q0) * i0;
            out[((b * A_ + 0) * C_ + c1) * HW_ + hwn] = a1 * rcpf(q1) * i1;
            out[((b * A_ + 1) * C_ + c0) * HW_ + hwn] = c0v * rcpf(r0) * i0;
            out[((b * A_ + 1) * C_ + c1) * HW_ + hwn] = c1v * rcpf(r1) * i1;
        }
    }
}

extern "C" void kernel_launch(void* const* d_in, const int* in_sizes, int n_in,
                              void* d_out, int out_size) {
    const float* scores = (const float*)d_in[0];
    const float* bbox = (const float*)d_in[1];
    const float* pp = (const float*)d_in[2];
    const float* dec = (const float*)d_in[3];
    float* out = (float*)d_out;

    k_fused<<<28, 256>>>(scores, pp, dec);
    k_main<<<512 + 88, 128>>>(bbox, pp, out);
}